// round 1
// baseline (speedup 1.0000x reference)
#include <cuda_runtime.h>

#define Bb   8
#define Nn   2048
#define FIN  128
#define FOUT 64
#define TI   64
#define TJ   64

// scratch (device globals: no allocations allowed)
__device__ float g_h[Bb * Nn * FOUT];
__device__ float g_s1[Bb * Nn];
__device__ float g_s2[Bb * Nn];

// ---------------- Kernel 1: h = x@W, s1 = h@a1, s2 = h@a2 ----------------
__global__ __launch_bounds__(256) void k1_proj(const float* __restrict__ x,
                                               const float* __restrict__ W,
                                               const float* __restrict__ a) {
    __shared__ float sW[FIN * FOUT];
    __shared__ float sa[2 * FOUT];
    int t = threadIdx.x;
    for (int i = t; i < FIN * FOUT; i += 256) sW[i] = W[i];
    if (t < 2 * FOUT) sa[t] = a[t];
    __syncthreads();

    int lane = t & 31;
    int warp = blockIdx.x * 8 + (t >> 5);
    for (int row = warp; row < Bb * Nn; row += gridDim.x * 8) {
        const float* xr = x + (size_t)row * FIN;
        float xv[4];
#pragma unroll
        for (int q = 0; q < 4; q++) xv[q] = xr[lane + 32 * q];
        float a0 = 0.f, a1 = 0.f;
#pragma unroll
        for (int k = 0; k < FIN; k++) {
            float xk = __shfl_sync(0xffffffffu, xv[k >> 5], k & 31);
            a0 = fmaf(xk, sW[k * FOUT + lane], a0);
            a1 = fmaf(xk, sW[k * FOUT + lane + 32], a1);
        }
        g_h[(size_t)row * FOUT + lane]      = a0;
        g_h[(size_t)row * FOUT + lane + 32] = a1;
        float p1 = a0 * sa[lane]      + a1 * sa[lane + 32];
        float p2 = a0 * sa[64 + lane] + a1 * sa[96 + lane];
#pragma unroll
        for (int o = 16; o; o >>= 1) {
            p1 += __shfl_xor_sync(0xffffffffu, p1, o);
            p2 += __shfl_xor_sync(0xffffffffu, p2, o);
        }
        if (lane == 0) { g_s1[row] = p1; g_s2[row] = p2; }
    }
}

// ---------------- fast exp of leakyrelu, masked (no MUFU) ----------------
// w = (m>0) ? exp(leakyrelu(t0, 0.2)) : 0
// exp(x) = 2^(x*log2e); magic-number round-to-nearest; degree-5 Taylor of 2^f
// on f in [-0.5,0.5] (max rel err ~2e-6); exponent spliced via integer add.
__device__ __forceinline__ float wfun(float t0, int m) {
    float lr = fmaxf(t0, 0.2f * t0);
    float tt = lr * 1.4426950408889634f;
    float fm = tt + 12582912.0f;           // 1.5*2^23 : round to nearest int
    float fi = fm - 12582912.0f;
    float f  = tt - fi;
    float p  = 0.0013333558146f;
    p = fmaf(p, f, 0.0096181291076f);
    p = fmaf(p, f, 0.0555041086648f);
    p = fmaf(p, f, 0.2402265069591f);
    p = fmaf(p, f, 0.6931471805599f);
    p = fmaf(p, f, 1.0f);
    int e = (__float_as_int(fm) - 0x4B400000) << 23;   // i << 23
    float r = __int_as_float(__float_as_int(p) + e);
    return (m > 0) ? r : 0.0f;
}

__device__ __forceinline__ unsigned long long pk2(float lo, float hi) {
    unsigned long long r;
    asm("mov.b64 %0, {%1, %2};" : "=l"(r) : "f"(lo), "f"(hi));
    return r;
}
#define FMA2(accv, aa, bb) \
    asm("fma.rn.f32x2 %0, %1, %2, %0;" : "+l"(accv) : "l"(aa), "l"(bb))

// ---------------- Kernel 2: fused masked softmax-attention + LN + ELU ----
// grid: (N/TI, B), 128 threads. Per block: rows [i0, i0+64) of batch b.
// Streams j in TJ=64 chunks: P-tile (exp weights) + h-tile in smem, then
// f32x2 register-tiled GEMM acc += P @ h. Denominator via P row-sums.
__global__ __launch_bounds__(128, 4) void k2_attn(const int* __restrict__ adj,
                                                  const float* __restrict__ gamma,
                                                  const float* __restrict__ beta,
                                                  float* __restrict__ out) {
    __shared__ float s_h[TJ * FOUT];       // 16 KB
    __shared__ float s_P[TI * 65];         // padded stride 65: conflict-free GEMM reads
    __shared__ float s_s1[TI];
    __shared__ float s_s2[TJ];
    __shared__ float s_dp[TI * 16];
    __shared__ float s_rd[TI];
    __shared__ float s_gb[2 * FOUT];

    int t  = threadIdx.x;
    int b  = blockIdx.y;
    int i0 = blockIdx.x * TI;
    const float* hb  = g_h + (size_t)b * Nn * FOUT;
    const int* adjb  = adj + (size_t)b * Nn * Nn + (size_t)i0 * Nn;

    if (t < TI) s_s1[t] = g_s1[b * Nn + i0 + t];
    s_gb[t] = (t < FOUT) ? gamma[t] : beta[t - FOUT];

    int tx = t & 7;        // f-group: cols tx*8 .. tx*8+7
    int ty = t >> 3;       // row-group: rows ty*4 .. ty*4+3
    int rg = t >> 4;       // P-gen row within pass
    int js = (t & 15) * 4; // P-gen j-segment

    unsigned long long acc[4][4];
#pragma unroll
    for (int r = 0; r < 4; r++)
#pragma unroll
        for (int c = 0; c < 4; c++) acc[r][c] = 0ull;
    float dpart[8];
#pragma unroll
    for (int p = 0; p < 8; p++) dpart[p] = 0.f;

    for (int j0 = 0; j0 < Nn; j0 += TJ) {
        __syncthreads();                       // prev GEMM done with s_P/s_h
        if (t < TJ) s_s2[t] = g_s2[b * Nn + j0 + t];
        {   // load h tile: 4096 floats = 1024 float4
            const float4* src = (const float4*)(hb + (size_t)j0 * FOUT);
            float4* dst = (float4*)s_h;
#pragma unroll
            for (int q = 0; q < 8; q++) dst[t + q * 128] = src[t + q * 128];
        }
        __syncthreads();
        // P generation: 8 passes x 4 elements per thread
#pragma unroll
        for (int p = 0; p < 8; p++) {
            int il = p * 8 + rg;
            int4 av = *(const int4*)(adjb + (size_t)il * Nn + j0 + js);
            float s1v = s_s1[il];
            float4 s2v = *(const float4*)&s_s2[js];
            float w0 = wfun(s1v + s2v.x, av.x);
            float w1 = wfun(s1v + s2v.y, av.y);
            float w2 = wfun(s1v + s2v.z, av.z);
            float w3 = wfun(s1v + s2v.w, av.w);
            float* pr = &s_P[il * 65 + js];
            pr[0] = w0; pr[1] = w1; pr[2] = w2; pr[3] = w3;
            dpart[p] += (w0 + w1) + (w2 + w3);
        }
        __syncthreads();
        // GEMM: acc[4][8f] += P[4rows][k] * h[k][8f], packed f32x2
#pragma unroll 8
        for (int k = 0; k < TJ; k++) {
            float4 hA = *(const float4*)&s_h[k * FOUT + tx * 8];
            float4 hB = *(const float4*)&s_h[k * FOUT + tx * 8 + 4];
            unsigned long long h0 = pk2(hA.x, hA.y);
            unsigned long long h1 = pk2(hA.z, hA.w);
            unsigned long long h2 = pk2(hB.x, hB.y);
            unsigned long long h3 = pk2(hB.z, hB.w);
#pragma unroll
            for (int r = 0; r < 4; r++) {
                float pv = s_P[(ty * 4 + r) * 65 + k];
                unsigned long long pp = pk2(pv, pv);
                FMA2(acc[r][0], pp, h0);
                FMA2(acc[r][1], pp, h1);
                FMA2(acc[r][2], pp, h2);
                FMA2(acc[r][3], pp, h3);
            }
        }
    }

    // denominator reduce
#pragma unroll
    for (int p = 0; p < 8; p++) s_dp[(p * 8 + rg) * 16 + (t & 15)] = dpart[p];
    __syncthreads();
    if (t < TI) {
        float s = 0.f;
#pragma unroll
        for (int q = 0; q < 16; q++) s += s_dp[t * 16 + q];
        s_rd[t] = __fdividef(1.0f, s);
    }
    __syncthreads();

    // epilogue: normalize, LayerNorm over 64 f (8 lanes x 8 regs), ELU, store
#pragma unroll
    for (int r = 0; r < 4; r++) {
        int row = ty * 4 + r;
        float rinv = s_rd[row];
        float v[8];
#pragma unroll
        for (int c = 0; c < 4; c++) {
            float lo, hi;
            asm("mov.b64 {%0, %1}, %2;" : "=f"(lo), "=f"(hi) : "l"(acc[r][c]));
            v[2 * c]     = lo * rinv;
            v[2 * c + 1] = hi * rinv;
        }
        float sum = ((v[0] + v[1]) + (v[2] + v[3])) + ((v[4] + v[5]) + (v[6] + v[7]));
        sum += __shfl_xor_sync(0xffffffffu, sum, 1);
        sum += __shfl_xor_sync(0xffffffffu, sum, 2);
        sum += __shfl_xor_sync(0xffffffffu, sum, 4);
        float mu = sum * (1.0f / 64.0f);
        float q = 0.f;
#pragma unroll
        for (int c = 0; c < 8; c++) { float d = v[c] - mu; q = fmaf(d, d, q); }
        q += __shfl_xor_sync(0xffffffffu, q, 1);
        q += __shfl_xor_sync(0xffffffffu, q, 2);
        q += __shfl_xor_sync(0xffffffffu, q, 4);
        float rstd = rsqrtf(q * (1.0f / 64.0f) + 1e-5f);
        float o[8];
#pragma unroll
        for (int c = 0; c < 8; c++) {
            float y = (v[c] - mu) * rstd * s_gb[tx * 8 + c] + s_gb[FOUT + tx * 8 + c];
            o[c] = (y > 0.f) ? y : (__expf(y) - 1.0f);
        }
        float4* op = (float4*)(out + ((size_t)(b * Nn + i0 + row) * FOUT + tx * 8));
        op[0] = make_float4(o[0], o[1], o[2], o[3]);
        op[1] = make_float4(o[4], o[5], o[6], o[7]);
    }
}

extern "C" void kernel_launch(void* const* d_in, const int* in_sizes, int n_in,
                              void* d_out, int out_size) {
    const float* x     = (const float*)d_in[0];
    const int*   adj   = (const int*)  d_in[1];
    const float* W     = (const float*)d_in[2];
    const float* a     = (const float*)d_in[3];
    const float* gamma = (const float*)d_in[4];
    const float* beta  = (const float*)d_in[5];
    float* out = (float*)d_out;

    k1_proj<<<512, 256>>>(x, W, a);
    k2_attn<<<dim3(Nn / TI, Bb), 128>>>(adj, gamma, beta, out);
}

// round 2
// speedup vs baseline: 1.0022x; 1.0022x over previous
#include <cuda_runtime.h>

#define Bb   8
#define Nn   2048
#define FIN  128
#define FOUT 64
#define TI   64
#define TJ   64

// scratch (device globals: no allocations allowed)
__device__ float g_h[Bb * Nn * FOUT];
__device__ float g_s1[Bb * Nn];
__device__ float g_s2[Bb * Nn];

// ---------------- Kernel 1: h = x@W, s1 = h@a1, s2 = h@a2 ----------------
__global__ __launch_bounds__(256) void k1_proj(const float* __restrict__ x,
                                               const float* __restrict__ W,
                                               const float* __restrict__ a) {
    __shared__ float sW[FIN * FOUT];
    __shared__ float sa[2 * FOUT];
    int t = threadIdx.x;
    for (int i = t; i < FIN * FOUT; i += 256) sW[i] = W[i];
    if (t < 2 * FOUT) sa[t] = a[t];
    __syncthreads();

    int lane = t & 31;
    int warp = blockIdx.x * 8 + (t >> 5);
    for (int row = warp; row < Bb * Nn; row += gridDim.x * 8) {
        const float* xr = x + (size_t)row * FIN;
        float xv[4];
#pragma unroll
        for (int q = 0; q < 4; q++) xv[q] = xr[lane + 32 * q];
        float a0 = 0.f, a1 = 0.f;
#pragma unroll
        for (int k = 0; k < FIN; k++) {
            float xk = __shfl_sync(0xffffffffu, xv[k >> 5], k & 31);
            a0 = fmaf(xk, sW[k * FOUT + lane], a0);
            a1 = fmaf(xk, sW[k * FOUT + lane + 32], a1);
        }
        g_h[(size_t)row * FOUT + lane]      = a0;
        g_h[(size_t)row * FOUT + lane + 32] = a1;
        float p1 = a0 * sa[lane]      + a1 * sa[lane + 32];
        float p2 = a0 * sa[64 + lane] + a1 * sa[96 + lane];
#pragma unroll
        for (int o = 16; o; o >>= 1) {
            p1 += __shfl_xor_sync(0xffffffffu, p1, o);
            p2 += __shfl_xor_sync(0xffffffffu, p2, o);
        }
        if (lane == 0) { g_s1[row] = p1; g_s2[row] = p2; }
    }
}

// ---------------- fast exp of leakyrelu, masked (no MUFU) ----------------
// w = (m>0) ? exp(leakyrelu(t0, 0.2)) : 0
// exp(x) = 2^(x*log2e); magic-number round-to-nearest; degree-5 Taylor of 2^f
// on f in [-0.5,0.5] (max rel err ~2e-6); exponent spliced via integer add.
__device__ __forceinline__ float wfun(float t0, int m) {
    float lr = fmaxf(t0, 0.2f * t0);
    float tt = lr * 1.4426950408889634f;
    float fm = tt + 12582912.0f;           // 1.5*2^23 : round to nearest int
    float fi = fm - 12582912.0f;
    float f  = tt - fi;
    float p  = 0.0013333558146f;
    p = fmaf(p, f, 0.0096181291076f);
    p = fmaf(p, f, 0.0555041086648f);
    p = fmaf(p, f, 0.2402265069591f);
    p = fmaf(p, f, 0.6931471805599f);
    p = fmaf(p, f, 1.0f);
    int e = (__float_as_int(fm) - 0x4B400000) << 23;   // i << 23
    float r = __int_as_float(__float_as_int(p) + e);
    return (m > 0) ? r : 0.0f;
}

__device__ __forceinline__ unsigned long long pk2(float lo, float hi) {
    unsigned long long r;
    asm("mov.b64 %0, {%1, %2};" : "=l"(r) : "f"(lo), "f"(hi));
    return r;
}
#define FMA2(accv, aa, bb) \
    asm("fma.rn.f32x2 %0, %1, %2, %0;" : "+l"(accv) : "l"(aa), "l"(bb))

// ---------------- Kernel 2: fused masked softmax-attention + LN + ELU ----
// grid: (N/TI, B), 128 threads. Per block: rows [i0, i0+64) of batch b.
// Streams j in TJ=64 chunks: P-tile (exp weights) + h-tile in smem, then
// f32x2 register-tiled GEMM acc += P @ h. Denominator via P row-sums.
__global__ __launch_bounds__(128, 4) void k2_attn(const int* __restrict__ adj,
                                                  const float* __restrict__ gamma,
                                                  const float* __restrict__ beta,
                                                  float* __restrict__ out) {
    __shared__ float s_h[TJ * FOUT];       // 16 KB
    __shared__ float s_P[TI * 65];         // padded stride 65: conflict-free GEMM reads
    __shared__ float s_s1[TI];
    __shared__ float s_s2[TJ];
    __shared__ float s_dp[TI * 16];
    __shared__ float s_rd[TI];
    __shared__ float s_gb[2 * FOUT];

    int t  = threadIdx.x;
    int b  = blockIdx.y;
    int i0 = blockIdx.x * TI;
    const float* hb  = g_h + (size_t)b * Nn * FOUT;
    const int* adjb  = adj + (size_t)b * Nn * Nn + (size_t)i0 * Nn;

    if (t < TI) s_s1[t] = g_s1[b * Nn + i0 + t];
    s_gb[t] = (t < FOUT) ? gamma[t] : beta[t - FOUT];

    int tx = t & 7;        // f-group: cols tx*8 .. tx*8+7
    int ty = t >> 3;       // row-group: rows ty*4 .. ty*4+3
    int rg = t >> 4;       // P-gen row within pass
    int js = (t & 15) * 4; // P-gen j-segment

    unsigned long long acc[4][4];
#pragma unroll
    for (int r = 0; r < 4; r++)
#pragma unroll
        for (int c = 0; c < 4; c++) acc[r][c] = 0ull;
    float dpart[8];
#pragma unroll
    for (int p = 0; p < 8; p++) dpart[p] = 0.f;

    for (int j0 = 0; j0 < Nn; j0 += TJ) {
        __syncthreads();                       // prev GEMM done with s_P/s_h
        if (t < TJ) s_s2[t] = g_s2[b * Nn + j0 + t];
        {   // load h tile: 4096 floats = 1024 float4
            const float4* src = (const float4*)(hb + (size_t)j0 * FOUT);
            float4* dst = (float4*)s_h;
#pragma unroll
            for (int q = 0; q < 8; q++) dst[t + q * 128] = src[t + q * 128];
        }
        __syncthreads();
        // P generation: 8 passes x 4 elements per thread
#pragma unroll
        for (int p = 0; p < 8; p++) {
            int il = p * 8 + rg;
            int4 av = *(const int4*)(adjb + (size_t)il * Nn + j0 + js);
            float s1v = s_s1[il];
            float4 s2v = *(const float4*)&s_s2[js];
            float w0 = wfun(s1v + s2v.x, av.x);
            float w1 = wfun(s1v + s2v.y, av.y);
            float w2 = wfun(s1v + s2v.z, av.z);
            float w3 = wfun(s1v + s2v.w, av.w);
            float* pr = &s_P[il * 65 + js];
            pr[0] = w0; pr[1] = w1; pr[2] = w2; pr[3] = w3;
            dpart[p] += (w0 + w1) + (w2 + w3);
        }
        __syncthreads();
        // GEMM: acc[4][8f] += P[4rows][k] * h[k][8f], packed f32x2
#pragma unroll 8
        for (int k = 0; k < TJ; k++) {
            float4 hA = *(const float4*)&s_h[k * FOUT + tx * 8];
            float4 hB = *(const float4*)&s_h[k * FOUT + tx * 8 + 4];
            unsigned long long h0 = pk2(hA.x, hA.y);
            unsigned long long h1 = pk2(hA.z, hA.w);
            unsigned long long h2 = pk2(hB.x, hB.y);
            unsigned long long h3 = pk2(hB.z, hB.w);
#pragma unroll
            for (int r = 0; r < 4; r++) {
                float pv = s_P[(ty * 4 + r) * 65 + k];
                unsigned long long pp = pk2(pv, pv);
                FMA2(acc[r][0], pp, h0);
                FMA2(acc[r][1], pp, h1);
                FMA2(acc[r][2], pp, h2);
                FMA2(acc[r][3], pp, h3);
            }
        }
    }

    // denominator reduce
#pragma unroll
    for (int p = 0; p < 8; p++) s_dp[(p * 8 + rg) * 16 + (t & 15)] = dpart[p];
    __syncthreads();
    if (t < TI) {
        float s = 0.f;
#pragma unroll
        for (int q = 0; q < 16; q++) s += s_dp[t * 16 + q];
        s_rd[t] = __fdividef(1.0f, s);
    }
    __syncthreads();

    // epilogue: normalize, LayerNorm over 64 f (8 lanes x 8 regs), ELU, store
#pragma unroll
    for (int r = 0; r < 4; r++) {
        int row = ty * 4 + r;
        float rinv = s_rd[row];
        float v[8];
#pragma unroll
        for (int c = 0; c < 4; c++) {
            float lo, hi;
            asm("mov.b64 {%0, %1}, %2;" : "=f"(lo), "=f"(hi) : "l"(acc[r][c]));
            v[2 * c]     = lo * rinv;
            v[2 * c + 1] = hi * rinv;
        }
        float sum = ((v[0] + v[1]) + (v[2] + v[3])) + ((v[4] + v[5]) + (v[6] + v[7]));
        sum += __shfl_xor_sync(0xffffffffu, sum, 1);
        sum += __shfl_xor_sync(0xffffffffu, sum, 2);
        sum += __shfl_xor_sync(0xffffffffu, sum, 4);
        float mu = sum * (1.0f / 64.0f);
        float q = 0.f;
#pragma unroll
        for (int c = 0; c < 8; c++) { float d = v[c] - mu; q = fmaf(d, d, q); }
        q += __shfl_xor_sync(0xffffffffu, q, 1);
        q += __shfl_xor_sync(0xffffffffu, q, 2);
        q += __shfl_xor_sync(0xffffffffu, q, 4);
        float rstd = rsqrtf(q * (1.0f / 64.0f) + 1e-5f);
        float o[8];
#pragma unroll
        for (int c = 0; c < 8; c++) {
            float y = (v[c] - mu) * rstd * s_gb[tx * 8 + c] + s_gb[FOUT + tx * 8 + c];
            o[c] = (y > 0.f) ? y : (__expf(y) - 1.0f);
        }
        float4* op = (float4*)(out + ((size_t)(b * Nn + i0 + row) * FOUT + tx * 8));
        op[0] = make_float4(o[0], o[1], o[2], o[3]);
        op[1] = make_float4(o[4], o[5], o[6], o[7]);
    }
}

extern "C" void kernel_launch(void* const* d_in, const int* in_sizes, int n_in,
                              void* d_out, int out_size) {
    const float* x     = (const float*)d_in[0];
    const int*   adj   = (const int*)  d_in[1];
    const float* W     = (const float*)d_in[2];
    const float* a     = (const float*)d_in[3];
    const float* gamma = (const float*)d_in[4];
    const float* beta  = (const float*)d_in[5];
    float* out = (float*)d_out;

    k1_proj<<<512, 256>>>(x, W, a);
    k2_attn<<<dim3(Nn / TI, Bb), 128>>>(adj, gamma, beta, out);
}

// round 4
// speedup vs baseline: 1.6684x; 1.6648x over previous
#include <cuda_runtime.h>
#include <cuda_bf16.h>

#define Bb   8
#define Nn   2048
#define FIN  128
#define FOUT 64
#define NSTRIP 4
#define JS   (Nn / NSTRIP)          // 512 j per strip
#define ROWS (Bb * Nn)              // 16384

typedef unsigned int u32;

// ---------------- device scratch (no allocations allowed) ----------------
__device__ float g_E1[ROWS], g_E2[ROWS], g_F1[ROWS], g_F2[ROWS];
__device__ __nv_bfloat16 g_hThi[ROWS * FOUT];
__device__ __nv_bfloat16 g_hTlo[ROWS * FOUT];
__device__ float g_part[NSTRIP * ROWS * FOUT];   // 16.8 MB partial numerators
__device__ float g_den [NSTRIP * ROWS];          // partial denominators

// ---------------- HMMA helpers (sm_80 baseline PTX: safe on sm_103) ------
__device__ __forceinline__ void ldsm4(u32& r0, u32& r1, u32& r2, u32& r3, u32 a) {
    asm volatile("ldmatrix.sync.aligned.m8n8.x4.shared.b16 {%0,%1,%2,%3}, [%4];"
                 : "=r"(r0), "=r"(r1), "=r"(r2), "=r"(r3) : "r"(a));
}
__device__ __forceinline__ void ldsm4t(u32& r0, u32& r1, u32& r2, u32& r3, u32 a) {
    asm volatile("ldmatrix.sync.aligned.m8n8.x4.trans.shared.b16 {%0,%1,%2,%3}, [%4];"
                 : "=r"(r0), "=r"(r1), "=r"(r2), "=r"(r3) : "r"(a));
}
__device__ __forceinline__ void hmma(float* c, const u32* a, u32 b0, u32 b1) {
    asm volatile("mma.sync.aligned.m16n8k16.row.col.f32.bf16.bf16.f32 "
                 "{%0,%1,%2,%3}, {%4,%5,%6,%7}, {%8,%9}, {%0,%1,%2,%3};"
                 : "+f"(c[0]), "+f"(c[1]), "+f"(c[2]), "+f"(c[3])
                 : "r"(a[0]), "r"(a[1]), "r"(a[2]), "r"(a[3]), "r"(b0), "r"(b1));
}
__device__ __forceinline__ u32 smem_u32(const void* p) {
    u32 a;
    asm("{ .reg .u64 t; cvta.to.shared.u64 t, %1; cvt.u32.u64 %0, t; }" : "=r"(a) : "l"(p));
    return a;
}

// ---------------- K1: h = x@W (bf16 hi/lo out), per-node exps ----------------
__global__ __launch_bounds__(256) void k1_proj(const float* __restrict__ x,
                                               const float* __restrict__ W,
                                               const float* __restrict__ a) {
    __shared__ float sW[FIN * FOUT];
    __shared__ float sa[2 * FOUT];
    int t = threadIdx.x;
    for (int i = t; i < FIN * FOUT; i += 256) sW[i] = W[i];
    if (t < 2 * FOUT) sa[t] = a[t];
    __syncthreads();

    int lane = t & 31;
    int warp = blockIdx.x * 8 + (t >> 5);
    for (int row = warp; row < ROWS; row += gridDim.x * 8) {
        const float* xr = x + (size_t)row * FIN;
        float xv[4];
#pragma unroll
        for (int q = 0; q < 4; q++) xv[q] = xr[lane + 32 * q];
        float a0 = 0.f, a1 = 0.f;
#pragma unroll
        for (int k = 0; k < FIN; k++) {
            float xk = __shfl_sync(0xffffffffu, xv[k >> 5], k & 31);
            a0 = fmaf(xk, sW[k * FOUT + lane], a0);
            a1 = fmaf(xk, sW[k * FOUT + lane + 32], a1);
        }
        // bf16 hi/lo split of h
        __nv_bfloat16 h0 = __float2bfloat16(a0);
        __nv_bfloat16 h1 = __float2bfloat16(a1);
        size_t o = (size_t)row * FOUT + lane;
        g_hThi[o]      = h0;
        g_hThi[o + 32] = h1;
        g_hTlo[o]      = __float2bfloat16(a0 - __bfloat162float(h0));
        g_hTlo[o + 32] = __float2bfloat16(a1 - __bfloat162float(h1));
        float p1 = a0 * sa[lane]      + a1 * sa[lane + 32];
        float p2 = a0 * sa[64 + lane] + a1 * sa[96 + lane];
#pragma unroll
        for (int o2 = 16; o2; o2 >>= 1) {
            p1 += __shfl_xor_sync(0xffffffffu, p1, o2);
            p2 += __shfl_xor_sync(0xffffffffu, p2, o2);
        }
        if (lane == 0) {
            g_E1[row] = __expf(p1);  g_E2[row] = __expf(0.2f * p1);
            g_F1[row] = __expf(p2);  g_F2[row] = __expf(0.2f * p2);
        }
    }
}

// ---------------- K2: masked-softmax attention numerator via HMMA ----------
// grid (32 i-tiles, 8 b, 4 strips), 128 threads (4 warps; warp owns 16 rows).
// Per 64-j chunk: h tile (bf16 hi/lo) + P tile (bf16 hi/lo) in smem, then
// per warp: 4 k-subs x 8 n-tiles x 3 HMMA into fp32 fragments.
#define PSTRB 144   // bytes per smem tile row (72 bf16: 64 + 8 pad)
__global__ __launch_bounds__(128, 5) void k2_attn(const int* __restrict__ adj) {
    __shared__ __align__(16) __nv_bfloat16 sPhi[64 * 72];
    __shared__ __align__(16) __nv_bfloat16 sPlo[64 * 72];
    __shared__ __align__(16) __nv_bfloat16 sHhi[64 * 72];
    __shared__ __align__(16) __nv_bfloat16 sHlo[64 * 72];
    __shared__ float2 sF[64];
    __shared__ float  sE1[64], sE2[64];
    __shared__ float  sdp[64 * 16];

    const int t = threadIdx.x, lane = t & 31, w = t >> 5;
    const int b = blockIdx.y, i0 = blockIdx.x * 64, strip = blockIdx.z;
    const int jbase = strip * JS;

    if (t < 64) { sE1[t] = g_E1[b * Nn + i0 + t]; sE2[t] = g_E2[b * Nn + i0 + t]; }

    const int rg = t >> 4, jsw = t & 15, js = jsw * 4;

    float acc[8][4];
#pragma unroll
    for (int n = 0; n < 8; n++)
#pragma unroll
        for (int q = 0; q < 4; q++) acc[n][q] = 0.f;
    float ds[8];
#pragma unroll
    for (int p = 0; p < 8; p++) ds[p] = 0.f;

    // ldmatrix addresses (constant per thread)
    const u32 pHiB = smem_u32(sPhi), pLoB = smem_u32(sPlo);
    const u32 hHiB = smem_u32(sHhi), hLoB = smem_u32(sHlo);
    const u32 aOff = (u32)(w * 16 + (lane & 15)) * PSTRB + (u32)((lane >> 4) & 1) * 16;
    const u32 hRow = (u32)((lane & 7) + ((lane >> 4) & 1) * 8);
    const u32 hCol = (u32)((lane >> 3) & 1) * 16;

    for (int c = 0; c < JS / 64; c++) {
        const int j0 = jbase + c * 64;
        __syncthreads();                              // previous MMA done
        // ---- phase 1: load h tiles (hi|lo) + F ----
        if (t < 64) sF[t] = make_float2(g_F1[b * Nn + j0 + t], g_F2[b * Nn + j0 + t]);
#pragma unroll
        for (int q = 0; q < 8; q++) {
            int u = t + q * 128;
            int seg = u >> 9, rem = u & 511;
            int row = rem >> 3, c16 = rem & 7;
            const __nv_bfloat16* src = (seg ? g_hTlo : g_hThi)
                                       + ((size_t)(b * Nn) + j0 + row) * FOUT + c16 * 8;
            uint4 v = *(const uint4*)src;
            char* dst = (char*)(seg ? sHlo : sHhi) + row * PSTRB + c16 * 16;
            *(uint4*)dst = v;
        }
        __syncthreads();
        // ---- phase 2: P-gen (bf16 hi/lo) ----
#pragma unroll
        for (int p = 0; p < 8; p++) {
            int il = p * 8 + rg;
            int4 av = *(const int4*)(adj + ((size_t)(b * Nn) + i0 + il) * Nn + j0 + js);
            float e1 = sE1[il], e2 = sE2[il];
            int ma[4] = {av.x, av.y, av.z, av.w};
            float wv[4];
#pragma unroll
            for (int q = 0; q < 4; q++) {
                float2 f = sF[js + q];
                float ww = fmaxf(e1 * f.x, e2 * f.y);
                wv[q] = (ma[q] > 0) ? ww : 0.f;
                ds[p] += wv[q];
            }
            __nv_bfloat162 h0 = __floats2bfloat162_rn(wv[0], wv[1]);
            __nv_bfloat162 h1 = __floats2bfloat162_rn(wv[2], wv[3]);
            __nv_bfloat162 l0 = __floats2bfloat162_rn(wv[0] - __low2float(h0),
                                                      wv[1] - __high2float(h0));
            __nv_bfloat162 l1 = __floats2bfloat162_rn(wv[2] - __low2float(h1),
                                                      wv[3] - __high2float(h1));
            *(uint2*)((char*)sPhi + il * PSTRB + js * 2) = make_uint2(*(u32*)&h0, *(u32*)&h1);
            *(uint2*)((char*)sPlo + il * PSTRB + js * 2) = make_uint2(*(u32*)&l0, *(u32*)&l1);
        }
        __syncthreads();
        // ---- phase 3: MMA ----
#pragma unroll
        for (int ks = 0; ks < 4; ks++) {
            u32 ahi[4], alo[4];
            ldsm4(ahi[0], ahi[1], ahi[2], ahi[3], pHiB + aOff + ks * 32);
            ldsm4(alo[0], alo[1], alo[2], alo[3], pLoB + aOff + ks * 32);
            u32 ho = (u32)(ks * 16 + hRow) * PSTRB + hCol;
#pragma unroll
            for (int np = 0; np < 4; np++) {
                u32 b0, b1, b2, b3, c0, c1, c2, c3;
                ldsm4t(b0, b1, b2, b3, hHiB + ho + np * 32);
                ldsm4t(c0, c1, c2, c3, hLoB + ho + np * 32);
                hmma(acc[np * 2],     ahi, b0, b2);
                hmma(acc[np * 2],     ahi, c0, c2);
                hmma(acc[np * 2],     alo, b0, b2);
                hmma(acc[np * 2 + 1], ahi, b1, b3);
                hmma(acc[np * 2 + 1], ahi, c1, c3);
                hmma(acc[np * 2 + 1], alo, b1, b3);
            }
        }
    }

    // ---- denominator partials ----
#pragma unroll
    for (int p = 0; p < 8; p++) sdp[(p * 8 + rg) * 16 + jsw] = ds[p];
    __syncthreads();
    if (t < 64) {
        float s = 0.f;
#pragma unroll
        for (int q = 0; q < 16; q++) s += sdp[t * 16 + q];
        g_den[(size_t)strip * ROWS + b * Nn + i0 + t] = s;
    }

    // ---- numerator partials: D fragments -> g_part ----
    float* base = g_part + (((size_t)strip * ROWS) + b * Nn + i0 + w * 16 + (lane >> 2))
                           * FOUT + (lane & 3) * 2;
#pragma unroll
    for (int nt = 0; nt < 8; nt++) {
        *(float2*)(base + nt * 8)            = make_float2(acc[nt][0], acc[nt][1]);
        *(float2*)(base + 8 * FOUT + nt * 8) = make_float2(acc[nt][2], acc[nt][3]);
    }
}

// ---------------- K3: combine strips, softmax-normalize, LN + ELU ----------
__global__ __launch_bounds__(256) void k3_fin(const float* __restrict__ gamma,
                                              const float* __restrict__ beta,
                                              float* __restrict__ out) {
    int warp = threadIdx.x >> 5, lane = threadIdx.x & 31;
    size_t row = (size_t)blockIdx.x * 8 + warp;
    int f0 = lane * 2;
    float2 v = make_float2(0.f, 0.f);
    float den = 0.f;
#pragma unroll
    for (int s = 0; s < NSTRIP; s++) {
        float2 pv = *(const float2*)(g_part + ((size_t)s * ROWS + row) * FOUT + f0);
        v.x += pv.x; v.y += pv.y;
        den += g_den[(size_t)s * ROWS + row];
    }
    float rinv = __fdividef(1.0f, den);
    v.x *= rinv; v.y *= rinv;
    float sum = v.x + v.y;
#pragma unroll
    for (int o = 16; o; o >>= 1) sum += __shfl_xor_sync(0xffffffffu, sum, o);
    float mu = sum * (1.0f / 64.0f);
    float dx = v.x - mu, dy = v.y - mu;
    float q = dx * dx + dy * dy;
#pragma unroll
    for (int o = 16; o; o >>= 1) q += __shfl_xor_sync(0xffffffffu, q, o);
    float rstd = rsqrtf(q * (1.0f / 64.0f) + 1e-5f);
    float y0 = dx * rstd * gamma[f0]     + beta[f0];
    float y1 = dy * rstd * gamma[f0 + 1] + beta[f0 + 1];
    float2 o2;
    o2.x = (y0 > 0.f) ? y0 : (__expf(y0) - 1.0f);
    o2.y = (y1 > 0.f) ? y1 : (__expf(y1) - 1.0f);
    *(float2*)(out + row * FOUT + f0) = o2;
}

extern "C" void kernel_launch(void* const* d_in, const int* in_sizes, int n_in,
                              void* d_out, int out_size) {
    const float* x     = (const float*)d_in[0];
    const int*   adj   = (const int*)  d_in[1];
    const float* W     = (const float*)d_in[2];
    const float* a     = (const float*)d_in[3];
    const float* gamma = (const float*)d_in[4];
    const float* beta  = (const float*)d_in[5];
    float* out = (float*)d_out;

    k1_proj<<<512, 256>>>(x, W, a);
    k2_attn<<<dim3(Nn / 64, Bb, NSTRIP), 128>>>(adj);
    k3_fin<<<ROWS / 8, 256>>>(gamma, beta, out);
}

// round 5
// speedup vs baseline: 2.5649x; 1.5374x over previous
#include <cuda_runtime.h>
#include <cuda_fp16.h>

#define Bb   8
#define Nn   2048
#define FIN  128
#define FOUT 64
#define NSTRIP 4
#define JS   (Nn / NSTRIP)          // 512 j per strip
#define ROWS (Bb * Nn)              // 16384

typedef unsigned int u32;

// ---------------- device scratch (no allocations allowed) ----------------
__device__ float g_E1[ROWS], g_E2[ROWS], g_F1[ROWS], g_F2[ROWS];
__device__ __half g_hHi[ROWS * FOUT];
__device__ __half g_hLo[ROWS * FOUT];
__device__ float g_part[NSTRIP * ROWS * FOUT];   // 16.8 MB partial numerators
__device__ float g_den [NSTRIP * ROWS];          // partial denominators

// ---------------- MMA helpers (sm_80 baseline PTX) ----------------
__device__ __forceinline__ void ldsm4(u32& r0, u32& r1, u32& r2, u32& r3, u32 a) {
    asm volatile("ldmatrix.sync.aligned.m8n8.x4.shared.b16 {%0,%1,%2,%3}, [%4];"
                 : "=r"(r0), "=r"(r1), "=r"(r2), "=r"(r3) : "r"(a));
}
__device__ __forceinline__ void ldsm4t(u32& r0, u32& r1, u32& r2, u32& r3, u32 a) {
    asm volatile("ldmatrix.sync.aligned.m8n8.x4.trans.shared.b16 {%0,%1,%2,%3}, [%4];"
                 : "=r"(r0), "=r"(r1), "=r"(r2), "=r"(r3) : "r"(a));
}
__device__ __forceinline__ void hmma(float* c, const u32* a, u32 b0, u32 b1) {
    asm volatile("mma.sync.aligned.m16n8k16.row.col.f32.f16.f16.f32 "
                 "{%0,%1,%2,%3}, {%4,%5,%6,%7}, {%8,%9}, {%0,%1,%2,%3};"
                 : "+f"(c[0]), "+f"(c[1]), "+f"(c[2]), "+f"(c[3])
                 : "r"(a[0]), "r"(a[1]), "r"(a[2]), "r"(a[3]), "r"(b0), "r"(b1));
}
__device__ __forceinline__ u32 smem_u32(const void* p) {
    u32 a;
    asm("{ .reg .u64 t; cvta.to.shared.u64 t, %1; cvt.u32.u64 %0, t; }" : "=r"(a) : "l"(p));
    return a;
}

// ---------------- K1: h = x@W (f16 hi/lo out), per-node exps ----------------
// grid 512, 128 threads; block computes 32 rows x 64 cols; thread tile 4x4.
__global__ __launch_bounds__(128) void k1_proj(const float* __restrict__ x,
                                               const float* __restrict__ W,
                                               const float* __restrict__ a) {
    __shared__ float sX[32][132];
    __shared__ float sW[FIN][FOUT];
    __shared__ float sa[2 * FOUT];
    __shared__ float sp1[32][17], sp2[32][17];

    int t = threadIdx.x;
    int r0 = blockIdx.x * 32;
#pragma unroll
    for (int q = 0; q < 16; q++)
        ((float4*)sW)[t + q * 128] = ((const float4*)W)[t + q * 128];
    sa[t] = a[t];
#pragma unroll
    for (int q = 0; q < 8; q++) {
        int idx = t + q * 128;
        int row = idx >> 5, c4 = idx & 31;
        *(float4*)&sX[row][c4 * 4] = ((const float4*)(x + (size_t)(r0 + row) * FIN))[c4];
    }
    __syncthreads();

    int rowt = t >> 4, colt = t & 15;
    float acc[4][4] = {};
#pragma unroll 4
    for (int k = 0; k < FIN; k++) {
        float4 wv = *(const float4*)&sW[k][colt * 4];
        float x0 = sX[rowt * 4 + 0][k], x1 = sX[rowt * 4 + 1][k];
        float x2 = sX[rowt * 4 + 2][k], x3 = sX[rowt * 4 + 3][k];
        acc[0][0] = fmaf(x0, wv.x, acc[0][0]); acc[0][1] = fmaf(x0, wv.y, acc[0][1]);
        acc[0][2] = fmaf(x0, wv.z, acc[0][2]); acc[0][3] = fmaf(x0, wv.w, acc[0][3]);
        acc[1][0] = fmaf(x1, wv.x, acc[1][0]); acc[1][1] = fmaf(x1, wv.y, acc[1][1]);
        acc[1][2] = fmaf(x1, wv.z, acc[1][2]); acc[1][3] = fmaf(x1, wv.w, acc[1][3]);
        acc[2][0] = fmaf(x2, wv.x, acc[2][0]); acc[2][1] = fmaf(x2, wv.y, acc[2][1]);
        acc[2][2] = fmaf(x2, wv.z, acc[2][2]); acc[2][3] = fmaf(x2, wv.w, acc[2][3]);
        acc[3][0] = fmaf(x3, wv.x, acc[3][0]); acc[3][1] = fmaf(x3, wv.y, acc[3][1]);
        acc[3][2] = fmaf(x3, wv.z, acc[3][2]); acc[3][3] = fmaf(x3, wv.w, acc[3][3]);
    }

    float a1v[4] = {sa[colt * 4], sa[colt * 4 + 1], sa[colt * 4 + 2], sa[colt * 4 + 3]};
    float a2v[4] = {sa[64 + colt * 4], sa[64 + colt * 4 + 1],
                    sa[64 + colt * 4 + 2], sa[64 + colt * 4 + 3]};
#pragma unroll
    for (int r = 0; r < 4; r++) {
        int row = rowt * 4 + r;
        float p1 = acc[r][0] * a1v[0] + acc[r][1] * a1v[1]
                 + acc[r][2] * a1v[2] + acc[r][3] * a1v[3];
        float p2 = acc[r][0] * a2v[0] + acc[r][1] * a2v[1]
                 + acc[r][2] * a2v[2] + acc[r][3] * a2v[3];
        sp1[row][colt] = p1;
        sp2[row][colt] = p2;
        // f16 hi/lo split store
        __half2 h0 = __floats2half2_rn(acc[r][0], acc[r][1]);
        __half2 h1 = __floats2half2_rn(acc[r][2], acc[r][3]);
        __half2 l0 = __floats2half2_rn(acc[r][0] - __low2float(h0),
                                       acc[r][1] - __high2float(h0));
        __half2 l1 = __floats2half2_rn(acc[r][2] - __low2float(h1),
                                       acc[r][3] - __high2float(h1));
        size_t o = (size_t)(r0 + row) * FOUT + colt * 4;
        *(uint2*)&g_hHi[o] = make_uint2(*(u32*)&h0, *(u32*)&h1);
        *(uint2*)&g_hLo[o] = make_uint2(*(u32*)&l0, *(u32*)&l1);
    }
    __syncthreads();
    if (t < 32) {
        float s1 = 0.f, s2 = 0.f;
#pragma unroll
        for (int q = 0; q < 16; q++) { s1 += sp1[t][q]; s2 += sp2[t][q]; }
        int gr = r0 + t;
        g_E1[gr] = __expf(s1);  g_E2[gr] = __expf(0.2f * s1);
        g_F1[gr] = __expf(s2);  g_F2[gr] = __expf(0.2f * s2);
    }
}

// ---------------- K2: masked-softmax attention numerator via HMMA ----------
// grid (32 i-tiles, 8 b, 4 strips), 128 threads (4 warps; warp owns 16 rows).
// P single-rounded fp16; h = fp16 hi+lo (2 MMAs per tile instead of 3).
#define PSTRB 144   // bytes per smem tile row (72 f16: 64 + 8 pad)
__global__ __launch_bounds__(128, 5) void k2_attn(const int* __restrict__ adj) {
    __shared__ __align__(16) __half sPh [64 * 72];
    __shared__ __align__(16) __half sHhi[64 * 72];
    __shared__ __align__(16) __half sHlo[64 * 72];
    __shared__ float2 sF[64];
    __shared__ float  sE1[64], sE2[64];
    __shared__ float  sdp[64 * 16];

    const int t = threadIdx.x, lane = t & 31, w = t >> 5;
    const int b = blockIdx.y, i0 = blockIdx.x * 64, strip = blockIdx.z;
    const int jbase = strip * JS;

    if (t < 64) { sE1[t] = g_E1[b * Nn + i0 + t]; sE2[t] = g_E2[b * Nn + i0 + t]; }

    const int rg = t >> 4, jsw = t & 15, js = jsw * 4;

    float acc[8][4];
#pragma unroll
    for (int n = 0; n < 8; n++)
#pragma unroll
        for (int q = 0; q < 4; q++) acc[n][q] = 0.f;
    float ds[8];
#pragma unroll
    for (int p = 0; p < 8; p++) ds[p] = 0.f;

    const u32 pHB = smem_u32(sPh);
    const u32 hHiB = smem_u32(sHhi), hLoB = smem_u32(sHlo);
    const u32 aOff = (u32)(w * 16 + (lane & 15)) * PSTRB + (u32)((lane >> 4) & 1) * 16;
    const u32 hRow = (u32)((lane & 7) + ((lane >> 4) & 1) * 8);
    const u32 hCol = (u32)((lane >> 3) & 1) * 16;

    for (int c = 0; c < JS / 64; c++) {
        const int j0 = jbase + c * 64;
        __syncthreads();                              // previous MMA done
        // ---- phase 1: load h tiles (hi|lo) + F ----
        if (t < 64) sF[t] = make_float2(g_F1[b * Nn + j0 + t], g_F2[b * Nn + j0 + t]);
#pragma unroll
        for (int q = 0; q < 8; q++) {
            int u = t + q * 128;
            int seg = u >> 9, rem = u & 511;
            int row = rem >> 3, c16 = rem & 7;
            const __half* src = (seg ? g_hLo : g_hHi)
                                + ((size_t)(b * Nn) + j0 + row) * FOUT + c16 * 8;
            uint4 v = *(const uint4*)src;
            char* dst = (char*)(seg ? sHlo : sHhi) + row * PSTRB + c16 * 16;
            *(uint4*)dst = v;
        }
        __syncthreads();
        // ---- phase 2: P-gen (single f16) ----
#pragma unroll
        for (int p = 0; p < 8; p++) {
            int il = p * 8 + rg;
            int4 av = *(const int4*)(adj + ((size_t)(b * Nn) + i0 + il) * Nn + j0 + js);
            float e1 = sE1[il], e2 = sE2[il];
            int ma[4] = {av.x, av.y, av.z, av.w};
            float wv[4];
#pragma unroll
            for (int q = 0; q < 4; q++) {
                float2 f = sF[js + q];
                float ww = fmaxf(e1 * f.x, e2 * f.y);
                wv[q] = (ma[q] > 0) ? ww : 0.f;
                ds[p] += wv[q];
            }
            __half2 q0 = __floats2half2_rn(wv[0], wv[1]);
            __half2 q1 = __floats2half2_rn(wv[2], wv[3]);
            *(uint2*)((char*)sPh + il * PSTRB + js * 2) = make_uint2(*(u32*)&q0, *(u32*)&q1);
        }
        __syncthreads();
        // ---- phase 3: MMA (2 terms: P*Hhi + P*Hlo) ----
#pragma unroll
        for (int ks = 0; ks < 4; ks++) {
            u32 af[4];
            ldsm4(af[0], af[1], af[2], af[3], pHB + aOff + ks * 32);
            u32 ho = (u32)(ks * 16 + hRow) * PSTRB + hCol;
#pragma unroll
            for (int np = 0; np < 4; np++) {
                u32 b0, b1, b2, b3, c0, c1, c2, c3;
                ldsm4t(b0, b1, b2, b3, hHiB + ho + np * 32);
                ldsm4t(c0, c1, c2, c3, hLoB + ho + np * 32);
                hmma(acc[np * 2],     af, b0, b2);
                hmma(acc[np * 2],     af, c0, c2);
                hmma(acc[np * 2 + 1], af, b1, b3);
                hmma(acc[np * 2 + 1], af, c1, c3);
            }
        }
    }

    // ---- denominator partials ----
#pragma unroll
    for (int p = 0; p < 8; p++) sdp[(p * 8 + rg) * 16 + jsw] = ds[p];
    __syncthreads();
    if (t < 64) {
        float s = 0.f;
#pragma unroll
        for (int q = 0; q < 16; q++) s += sdp[t * 16 + q];
        g_den[(size_t)strip * ROWS + b * Nn + i0 + t] = s;
    }

    // ---- numerator partials: D fragments -> g_part ----
    float* base = g_part + (((size_t)strip * ROWS) + b * Nn + i0 + w * 16 + (lane >> 2))
                           * FOUT + (lane & 3) * 2;
#pragma unroll
    for (int nt = 0; nt < 8; nt++) {
        *(float2*)(base + nt * 8)            = make_float2(acc[nt][0], acc[nt][1]);
        *(float2*)(base + 8 * FOUT + nt * 8) = make_float2(acc[nt][2], acc[nt][3]);
    }
}

// ---------------- K3: combine strips, softmax-normalize, LN + ELU ----------
__global__ __launch_bounds__(256) void k3_fin(const float* __restrict__ gamma,
                                              const float* __restrict__ beta,
                                              float* __restrict__ out) {
    int warp = threadIdx.x >> 5, lane = threadIdx.x & 31;
    size_t row = (size_t)blockIdx.x * 8 + warp;
    int f0 = lane * 2;
    float2 v = make_float2(0.f, 0.f);
    float den = 0.f;
#pragma unroll
    for (int s = 0; s < NSTRIP; s++) {
        float2 pv = *(const float2*)(g_part + ((size_t)s * ROWS + row) * FOUT + f0);
        v.x += pv.x; v.y += pv.y;
        den += g_den[(size_t)s * ROWS + row];
    }
    float rinv = __fdividef(1.0f, den);
    v.x *= rinv; v.y *= rinv;
    float sum = v.x + v.y;
#pragma unroll
    for (int o = 16; o; o >>= 1) sum += __shfl_xor_sync(0xffffffffu, sum, o);
    float mu = sum * (1.0f / 64.0f);
    float dx = v.x - mu, dy = v.y - mu;
    float q = dx * dx + dy * dy;
#pragma unroll
    for (int o = 16; o; o >>= 1) q += __shfl_xor_sync(0xffffffffu, q, o);
    float rstd = rsqrtf(q * (1.0f / 64.0f) + 1e-5f);
    float y0 = dx * rstd * gamma[f0]     + beta[f0];
    float y1 = dy * rstd * gamma[f0 + 1] + beta[f0 + 1];
    float2 o2;
    o2.x = (y0 > 0.f) ? y0 : (__expf(y0) - 1.0f);
    o2.y = (y1 > 0.f) ? y1 : (__expf(y1) - 1.0f);
    *(float2*)(out + row * FOUT + f0) = o2;
}

extern "C" void kernel_launch(void* const* d_in, const int* in_sizes, int n_in,
                              void* d_out, int out_size) {
    const float* x     = (const float*)d_in[0];
    const int*   adj   = (const int*)  d_in[1];
    const float* W     = (const float*)d_in[2];
    const float* a     = (const float*)d_in[3];
    const float* gamma = (const float*)d_in[4];
    const float* beta  = (const float*)d_in[5];
    float* out = (float*)d_out;

    k1_proj<<<ROWS / 32, 128>>>(x, W, a);
    k2_attn<<<dim3(Nn / 64, Bb, NSTRIP), 128>>>(adj);
    k3_fin<<<ROWS / 8, 256>>>(gamma, beta, out);
}

// round 6
// speedup vs baseline: 2.6423x; 1.0302x over previous
#include <cuda_runtime.h>
#include <cuda_fp16.h>

#define Bb   8
#define Nn   2048
#define FIN  128
#define FOUT 64
#define NSTRIP 4
#define JS   (Nn / NSTRIP)          // 512 j per strip
#define ROWS (Bb * Nn)              // 16384
#define K1BLK 512                   // k1 blocks inside fused kernel
#define PACKBLK (ROWS / 4)          // 4096 pack blocks (4 warps x 1 row)

typedef unsigned int u32;
typedef unsigned long long u64;

// ---------------- device scratch (no allocations allowed) ----------------
__device__ float g_E1[ROWS], g_E2[ROWS], g_F1[ROWS], g_F2[ROWS];
__device__ __half g_hHi[ROWS * FOUT];
__device__ __half g_hLo[ROWS * FOUT];
__device__ u32   g_mask[ROWS * 64];              // 4.2 MB adjacency bitmask
__device__ float g_part[NSTRIP * ROWS * FOUT];   // 16.8 MB partial numerators
__device__ float g_den [NSTRIP * ROWS];          // partial denominators

// ---------------- MMA helpers (sm_80 baseline PTX) ----------------
__device__ __forceinline__ void ldsm4(u32& r0, u32& r1, u32& r2, u32& r3, u32 a) {
    asm volatile("ldmatrix.sync.aligned.m8n8.x4.shared.b16 {%0,%1,%2,%3}, [%4];"
                 : "=r"(r0), "=r"(r1), "=r"(r2), "=r"(r3) : "r"(a));
}
__device__ __forceinline__ void ldsm4t(u32& r0, u32& r1, u32& r2, u32& r3, u32 a) {
    asm volatile("ldmatrix.sync.aligned.m8n8.x4.trans.shared.b16 {%0,%1,%2,%3}, [%4];"
                 : "=r"(r0), "=r"(r1), "=r"(r2), "=r"(r3) : "r"(a));
}
__device__ __forceinline__ void ldsm2t(u32& r0, u32& r1, u32 a) {
    asm volatile("ldmatrix.sync.aligned.m8n8.x2.trans.shared.b16 {%0,%1}, [%2];"
                 : "=r"(r0), "=r"(r1) : "r"(a));
}
__device__ __forceinline__ void hmma(float* c, const u32* a, u32 b0, u32 b1) {
    asm volatile("mma.sync.aligned.m16n8k16.row.col.f32.f16.f16.f32 "
                 "{%0,%1,%2,%3}, {%4,%5,%6,%7}, {%8,%9}, {%0,%1,%2,%3};"
                 : "+f"(c[0]), "+f"(c[1]), "+f"(c[2]), "+f"(c[3])
                 : "r"(a[0]), "r"(a[1]), "r"(a[2]), "r"(a[3]), "r"(b0), "r"(b1));
}
__device__ __forceinline__ u32 smem_u32(const void* p) {
    u32 a;
    asm("{ .reg .u64 t; cvta.to.shared.u64 t, %1; cvt.u32.u64 %0, t; }" : "=r"(a) : "l"(p));
    return a;
}

// ---------------- K1 fused: proj (blocks < K1BLK) + adj bit-pack ----------
__global__ __launch_bounds__(128) void k1_fused(const float* __restrict__ x,
                                                const float* __restrict__ W,
                                                const float* __restrict__ a,
                                                const int* __restrict__ adj) {
    __shared__ float sX[32][132];
    __shared__ float sW[FIN][FOUT];
    __shared__ float sa[2 * FOUT];
    __shared__ float sp1[32][17], sp2[32][17];

    int t = threadIdx.x;
    if (blockIdx.x >= K1BLK) {
        // ---- adjacency bit-pack: warp per row, ballot per 32 j ----
        int lane = t & 31;
        int row = (blockIdx.x - K1BLK) * 4 + (t >> 5);
        const int* rowp = adj + (size_t)row * Nn;
        u32* mrow = g_mask + (size_t)row * 64;
        for (int c = 0; c < 64; c += 8) {
            int v[8];
#pragma unroll
            for (int q = 0; q < 8; q++) v[q] = rowp[(c + q) * 32 + lane];
            u32 bm[8];
#pragma unroll
            for (int q = 0; q < 8; q++) bm[q] = __ballot_sync(0xffffffffu, v[q] > 0);
            if (lane < 4)
                *(uint2*)&mrow[c + lane * 2] = make_uint2(bm[lane * 2], bm[lane * 2 + 1]);
        }
        return;
    }

    // ---- projection: h = x@W (f16 hi/lo), per-node exps ----
    int r0 = blockIdx.x * 32;
#pragma unroll
    for (int q = 0; q < 16; q++)
        ((float4*)sW)[t + q * 128] = ((const float4*)W)[t + q * 128];
    sa[t] = a[t];
#pragma unroll
    for (int q = 0; q < 8; q++) {
        int idx = t + q * 128;
        int row = idx >> 5, c4 = idx & 31;
        *(float4*)&sX[row][c4 * 4] = ((const float4*)(x + (size_t)(r0 + row) * FIN))[c4];
    }
    __syncthreads();

    int rowt = t >> 4, colt = t & 15;
    float acc[4][4] = {};
#pragma unroll 4
    for (int k = 0; k < FIN; k++) {
        float4 wv = *(const float4*)&sW[k][colt * 4];
        float x0 = sX[rowt * 4 + 0][k], x1 = sX[rowt * 4 + 1][k];
        float x2 = sX[rowt * 4 + 2][k], x3 = sX[rowt * 4 + 3][k];
        acc[0][0] = fmaf(x0, wv.x, acc[0][0]); acc[0][1] = fmaf(x0, wv.y, acc[0][1]);
        acc[0][2] = fmaf(x0, wv.z, acc[0][2]); acc[0][3] = fmaf(x0, wv.w, acc[0][3]);
        acc[1][0] = fmaf(x1, wv.x, acc[1][0]); acc[1][1] = fmaf(x1, wv.y, acc[1][1]);
        acc[1][2] = fmaf(x1, wv.z, acc[1][2]); acc[1][3] = fmaf(x1, wv.w, acc[1][3]);
        acc[2][0] = fmaf(x2, wv.x, acc[2][0]); acc[2][1] = fmaf(x2, wv.y, acc[2][1]);
        acc[2][2] = fmaf(x2, wv.z, acc[2][2]); acc[2][3] = fmaf(x2, wv.w, acc[2][3]);
        acc[3][0] = fmaf(x3, wv.x, acc[3][0]); acc[3][1] = fmaf(x3, wv.y, acc[3][1]);
        acc[3][2] = fmaf(x3, wv.z, acc[3][2]); acc[3][3] = fmaf(x3, wv.w, acc[3][3]);
    }

    float a1v[4] = {sa[colt * 4], sa[colt * 4 + 1], sa[colt * 4 + 2], sa[colt * 4 + 3]};
    float a2v[4] = {sa[64 + colt * 4], sa[64 + colt * 4 + 1],
                    sa[64 + colt * 4 + 2], sa[64 + colt * 4 + 3]};
#pragma unroll
    for (int r = 0; r < 4; r++) {
        int row = rowt * 4 + r;
        float p1 = acc[r][0] * a1v[0] + acc[r][1] * a1v[1]
                 + acc[r][2] * a1v[2] + acc[r][3] * a1v[3];
        float p2 = acc[r][0] * a2v[0] + acc[r][1] * a2v[1]
                 + acc[r][2] * a2v[2] + acc[r][3] * a2v[3];
        sp1[row][colt] = p1;
        sp2[row][colt] = p2;
        __half2 h0 = __floats2half2_rn(acc[r][0], acc[r][1]);
        __half2 h1 = __floats2half2_rn(acc[r][2], acc[r][3]);
        __half2 l0 = __floats2half2_rn(acc[r][0] - __low2float(h0),
                                       acc[r][1] - __high2float(h0));
        __half2 l1 = __floats2half2_rn(acc[r][2] - __low2float(h1),
                                       acc[r][3] - __high2float(h1));
        size_t o = (size_t)(r0 + row) * FOUT + colt * 4;
        *(uint2*)&g_hHi[o] = make_uint2(*(u32*)&h0, *(u32*)&h1);
        *(uint2*)&g_hLo[o] = make_uint2(*(u32*)&l0, *(u32*)&l1);
    }
    __syncthreads();
    if (t < 32) {
        float s1 = 0.f, s2 = 0.f;
#pragma unroll
        for (int q = 0; q < 16; q++) { s1 += sp1[t][q]; s2 += sp2[t][q]; }
        int gr = r0 + t;
        g_E1[gr] = __expf(s1);  g_E2[gr] = __expf(0.2f * s1);
        g_F1[gr] = __expf(s2);  g_F2[gr] = __expf(0.2f * s2);
    }
}

// ---------------- K2: masked-softmax attention numerator via HMMA ----------
// grid (32 i-tiles, 8 b, 4 strips), 128 threads. adj via bitmask (L1-resident).
// Denominator computed by the MMA itself: ones-column at h-tile col 64.
#define PSTRB 144   // bytes per smem tile row (72 f16: 64 data + 8 pad/ones)
__global__ __launch_bounds__(128, 5) void k2_attn() {
    __shared__ __align__(16) __half sPh [64 * 72];
    __shared__ __align__(16) __half sHhi[64 * 72];
    __shared__ __align__(16) __half sHlo[64 * 72];
    __shared__ float2 sF[64];
    __shared__ float  sE1[64], sE2[64];

    const int t = threadIdx.x, lane = t & 31, w = t >> 5;
    const int b = blockIdx.y, i0 = blockIdx.x * 64, strip = blockIdx.z;
    const int jbase = strip * JS;

    if (t < 64) { sE1[t] = g_E1[b * Nn + i0 + t]; sE2[t] = g_E2[b * Nn + i0 + t]; }
    // ones-column init (cols 64-71 pad region, written once; phase1 never touches it)
    if (t < 64) {
        *(uint4*)((char*)sHhi + t * PSTRB + 128) = make_uint4(0x00003C00u, 0, 0, 0);
        *(uint4*)((char*)sHlo + t * PSTRB + 128) = make_uint4(0, 0, 0, 0);
    }

    const int rg = t >> 4, jsw = t & 15, js = jsw * 4;
    const u32* mrow = g_mask + (size_t)(b * Nn + i0) * 64;
    const int mcol = jsw >> 3, msh = (jsw & 7) * 4;

    float acc[8][4];
#pragma unroll
    for (int n = 0; n < 8; n++)
#pragma unroll
        for (int q = 0; q < 4; q++) acc[n][q] = 0.f;
    float accD[4] = {0.f, 0.f, 0.f, 0.f};

    const u32 pHB = smem_u32(sPh);
    const u32 hHiB = smem_u32(sHhi), hLoB = smem_u32(sHlo);
    const u32 aOff = (u32)(w * 16 + (lane & 15)) * PSTRB + (u32)((lane >> 4) & 1) * 16;
    const u32 hRow = (u32)((lane & 7) + ((lane >> 4) & 1) * 8);
    const u32 hCol = (u32)((lane >> 3) & 1) * 16;
    const u32 oRow = (u32)((lane & 7) + ((lane >> 3) & 3 & 1) * 8); // lanes 0-15 matter
    const u32 oAddr0 = (u32)((lane & 15)) * PSTRB;                  // row base for ldsm2t

    for (int c = 0; c < JS / 64; c++) {
        const int j0 = jbase + c * 64;
        __syncthreads();                              // previous MMA done
        // ---- phase 1: load h tiles (hi|lo) + F + mask words ----
        if (t < 64) sF[t] = make_float2(g_F1[b * Nn + j0 + t], g_F2[b * Nn + j0 + t]);
        u32 mw[8];
        {
            const int wbase = (j0 >> 5) + mcol;
#pragma unroll
            for (int p = 0; p < 8; p++)
                mw[p] = mrow[(size_t)(p * 8 + rg) * 64 + wbase];
        }
#pragma unroll
        for (int q = 0; q < 8; q++) {
            int u = t + q * 128;
            int seg = u >> 9, rem = u & 511;
            int row = rem >> 3, c16 = rem & 7;
            const __half* src = (seg ? g_hLo : g_hHi)
                                + ((size_t)(b * Nn) + j0 + row) * FOUT + c16 * 8;
            uint4 v = *(const uint4*)src;
            char* dst = (char*)(seg ? sHlo : sHhi) + row * PSTRB + c16 * 16;
            *(uint4*)dst = v;
        }
        __syncthreads();
        // ---- phase 2: P-gen (single f16 round) ----
        float2 f0 = sF[js], f1 = sF[js + 1], f2 = sF[js + 2], f3 = sF[js + 3];
#pragma unroll
        for (int p = 0; p < 8; p++) {
            int il = p * 8 + rg;
            float e1 = sE1[il], e2 = sE2[il];
            u32 nib = mw[p] >> msh;
            float w0 = (nib & 1u)      ? fmaxf(e1 * f0.x, e2 * f0.y) : 0.f;
            float w1 = ((nib >> 1) & 1u) ? fmaxf(e1 * f1.x, e2 * f1.y) : 0.f;
            float w2 = ((nib >> 2) & 1u) ? fmaxf(e1 * f2.x, e2 * f2.y) : 0.f;
            float w3 = ((nib >> 3) & 1u) ? fmaxf(e1 * f3.x, e2 * f3.y) : 0.f;
            __half2 q0 = __floats2half2_rn(w0, w1);
            __half2 q1 = __floats2half2_rn(w2, w3);
            *(uint2*)((char*)sPh + il * PSTRB + js * 2) = make_uint2(*(u32*)&q0, *(u32*)&q1);
        }
        __syncthreads();
        // ---- phase 3: MMA (P*Hhi + P*Hlo + P*ones) ----
#pragma unroll
        for (int ks = 0; ks < 4; ks++) {
            u32 af[4];
            ldsm4(af[0], af[1], af[2], af[3], pHB + aOff + ks * 32);
            u32 ho = (u32)(ks * 16 + hRow) * PSTRB + hCol;
#pragma unroll
            for (int np = 0; np < 4; np++) {
                u32 b0, b1, b2, b3, c0, c1, c2, c3;
                ldsm4t(b0, b1, b2, b3, hHiB + ho + np * 32);
                ldsm4t(c0, c1, c2, c3, hLoB + ho + np * 32);
                hmma(acc[np * 2],     af, b0, b2);
                hmma(acc[np * 2],     af, c0, c2);
                hmma(acc[np * 2 + 1], af, b1, b3);
                hmma(acc[np * 2 + 1], af, c1, c3);
            }
            u32 d0, d1;
            ldsm2t(d0, d1, hHiB + (u32)(ks * 16) * PSTRB + oAddr0 + 128);
            hmma(accD, af, d0, d1);
        }
    }

    // ---- denominator (col 64 of ones-tile): lanes with lane%4==0 hold it ----
    if ((lane & 3) == 0) {
        size_t dbase = (size_t)strip * ROWS + b * Nn + i0 + w * 16 + (lane >> 2);
        g_den[dbase]     = accD[0];
        g_den[dbase + 8] = accD[2];
    }

    // ---- numerator partials: D fragments -> g_part ----
    float* base = g_part + (((size_t)strip * ROWS) + b * Nn + i0 + w * 16 + (lane >> 2))
                           * FOUT + (lane & 3) * 2;
#pragma unroll
    for (int nt = 0; nt < 8; nt++) {
        *(float2*)(base + nt * 8)            = make_float2(acc[nt][0], acc[nt][1]);
        *(float2*)(base + 8 * FOUT + nt * 8) = make_float2(acc[nt][2], acc[nt][3]);
    }
}

// ---------------- K3: combine strips, softmax-normalize, LN + ELU ----------
__global__ __launch_bounds__(256) void k3_fin(const float* __restrict__ gamma,
                                              const float* __restrict__ beta,
                                              float* __restrict__ out) {
    int warp = threadIdx.x >> 5, lane = threadIdx.x & 31;
    size_t row = (size_t)blockIdx.x * 8 + warp;
    int f0 = lane * 2;
    float2 v = make_float2(0.f, 0.f);
    float den = 0.f;
#pragma unroll
    for (int s = 0; s < NSTRIP; s++) {
        float2 pv = *(const float2*)(g_part + ((size_t)s * ROWS + row) * FOUT + f0);
        v.x += pv.x; v.y += pv.y;
        den += g_den[(size_t)s * ROWS + row];
    }
    float rinv = __fdividef(1.0f, den);
    v.x *= rinv; v.y *= rinv;
    float sum = v.x + v.y;
#pragma unroll
    for (int o = 16; o; o >>= 1) sum += __shfl_xor_sync(0xffffffffu, sum, o);
    float mu = sum * (1.0f / 64.0f);
    float dx = v.x - mu, dy = v.y - mu;
    float q = dx * dx + dy * dy;
#pragma unroll
    for (int o = 16; o; o >>= 1) q += __shfl_xor_sync(0xffffffffu, q, o);
    float rstd = rsqrtf(q * (1.0f / 64.0f) + 1e-5f);
    float y0 = dx * rstd * gamma[f0]     + beta[f0];
    float y1 = dy * rstd * gamma[f0 + 1] + beta[f0 + 1];
    float2 o2;
    o2.x = (y0 > 0.f) ? y0 : (__expf(y0) - 1.0f);
    o2.y = (y1 > 0.f) ? y1 : (__expf(y1) - 1.0f);
    *(float2*)(out + row * FOUT + f0) = o2;
}

extern "C" void kernel_launch(void* const* d_in, const int* in_sizes, int n_in,
                              void* d_out, int out_size) {
    const float* x     = (const float*)d_in[0];
    const int*   adj   = (const int*)  d_in[1];
    const float* W     = (const float*)d_in[2];
    const float* a     = (const float*)d_in[3];
    const float* gamma = (const float*)d_in[4];
    const float* beta  = (const float*)d_in[5];
    float* out = (float*)d_out;

    k1_fused<<<K1BLK + PACKBLK, 128>>>(x, W, a, adj);
    k2_attn<<<dim3(Nn / 64, Bb, NSTRIP), 128>>>();
    k3_fin<<<ROWS / 8, 256>>>(gamma, beta, out);
}